// round 5
// baseline (speedup 1.0000x reference)
#include <cuda_runtime.h>

// Fused persistent LSTM + MLP classifier, v3.
// R4 evidence: L1(shared)=76%, fma=39.8%, issue=40% -> SMEM-crossbar bound,
// dominated by streaming Wc (116 KB/step/block) through LDS every timestep.
// v3: weights live in REGISTERS for the whole kernel (114 floats/thread,
// k-loop fully unrolled), SMEM keeps only act/partials. GEMM SMEM traffic is
// now pure broadcast act reads. Cell phase uses all 256 threads.
//
// grid=128 blocks (8 batch rows), 256 threads:
//   GEMM role: thread = (gp in [0,128): gates 2gp,2gp+1) x (kh in {0,1}: K
//     half of 57). acc = f32x2 {row even, row odd} x 4 rowpairs x 2 gates.
//   Cell role: thread = (u = tid&63, rp = tid>>6): unit u, rows 2rp,2rp+1,
//     c packed f32x2; reads part[0]+part[1], writes h to act.

namespace {

constexpr int Bn   = 1024;
constexpr int Sn   = 512;
constexpr int In   = 50;
constexpr int Hn   = 64;
constexpr int F1n  = 32;
constexpr int Cn   = 2;
constexpr int KTOT = Hn + In;    // 114
constexpr int KH   = 57;         // K half per thread
constexpr int TB   = 8;
constexpr int GRID = Bn / TB;    // 128
constexpr int NT   = 256;

struct Smem {
  float act[KTOT][TB];       // [k][row] (k<64: h, else x_t)        3648 B
  float part[2][4][128][4];  // [kh][rp][gp][{g0r0,g0r1,g1r0,g1r1}] 16384 B
  float f1[TB][F1n];         //                                     1024 B
};

using u64 = unsigned long long;

__device__ __forceinline__ u64 pack2(float lo, float hi) {
  u64 r;
  asm("mov.b64 %0, {%1, %2};" : "=l"(r)
      : "r"(__float_as_uint(lo)), "r"(__float_as_uint(hi)));
  return r;
}
__device__ __forceinline__ void unpack2(u64 v, float& lo, float& hi) {
  unsigned a, b;
  asm("mov.b64 {%0, %1}, %2;" : "=r"(a), "=r"(b) : "l"(v));
  lo = __uint_as_float(a);
  hi = __uint_as_float(b);
}
__device__ __forceinline__ u64 fma2(u64 a, u64 b, u64 c) {
  u64 d;
  asm("fma.rn.f32x2 %0, %1, %2, %3;" : "=l"(d) : "l"(a), "l"(b), "l"(c));
  return d;
}
__device__ __forceinline__ u64 add2(u64 a, u64 b) {
  u64 d;
  asm("add.rn.f32x2 %0, %1, %2;" : "=l"(d) : "l"(a), "l"(b));
  return d;
}
__device__ __forceinline__ float tanh_ap(float x) {
  float y;
  asm("tanh.approx.f32 %0, %1;" : "=f"(y) : "f"(x));
  return y;
}
__device__ __forceinline__ float sigmoid_ap(float x) {
  return fmaf(0.5f, tanh_ap(0.5f * x), 0.5f);
}

__global__ __launch_bounds__(NT, 1) void lstm_fused(
    const float* __restrict__ x,
    const float* __restrict__ W_ih, const float* __restrict__ W_hh,
    const float* __restrict__ b_ih, const float* __restrict__ b_hh,
    const float* __restrict__ W1,   const float* __restrict__ b1,
    const float* __restrict__ W2,   const float* __restrict__ b2,
    float* __restrict__ out) {
  __shared__ Smem s;

  const int tid  = threadIdx.x;
  const int row0 = blockIdx.x * TB;

  // ---- roles ----
  const int gp = tid & 127;          // gate pair: gates 2gp, 2gp+1
  const int kh = tid >> 7;           // K half
  const int k0 = kh * KH;
  const int cu = tid & 63;           // cell: unit
  const int crp = tid >> 6;          // cell: row pair (rows 2crp, 2crp+1)

  // ---- load this thread's weight slice into registers (time-invariant) ----
  float wr0[KH], wr1[KH];
  {
    const int g0 = 2 * gp, g1 = 2 * gp + 1;
#pragma unroll
    for (int j = 0; j < KH; j++) {
      const int k = k0 + j;
      wr0[j] = (k < Hn) ? W_hh[g0 * Hn + k] : W_ih[g0 * In + (k - Hn)];
      wr1[j] = (k < Hn) ? W_hh[g1 * Hn + k] : W_ih[g1 * In + (k - Hn)];
    }
  }
  u64 bias2[2];
  {
    const float bb0 = (kh == 0) ? b_ih[2 * gp] + b_hh[2 * gp] : 0.0f;
    const float bb1 = (kh == 0) ? b_ih[2 * gp + 1] + b_hh[2 * gp + 1] : 0.0f;
    bias2[0] = pack2(bb0, bb0);
    bias2[1] = pack2(bb1, bb1);
  }

  // ---- init act: h = 0, x_t0 ----
  for (int idx = tid; idx < Hn * TB; idx += NT)
    (&s.act[0][0])[idx] = 0.0f;

  // t-invariant x-prefetch slots: TB*In = 400 over 256 thr x 2
  int  xr_i2[2], xr_row2[2];
  bool xr_ok[2];
  const float* xr_ptr[2];
#pragma unroll
  for (int j = 0; j < 2; j++) {
    int idx   = tid + NT * j;
    xr_ok[j]  = (idx < TB * In);
    int r     = idx / In;
    int i     = idx - r * In;
    if (!xr_ok[j]) { r = 0; i = 0; }
    xr_row2[j] = r;
    xr_i2[j]   = i;
    xr_ptr[j]  = x + (long)(row0 + r) * (Sn * In) + i;
  }
#pragma unroll
  for (int j = 0; j < 2; j++)
    if (xr_ok[j]) s.act[Hn + xr_i2[j]][xr_row2[j]] = xr_ptr[j][0];

  __syncthreads();

  u64 c2 = 0ull;  // cell state {row even, row odd} for unit cu

  for (int t = 0; t < Sn; t++) {
    // prefetch next x (hidden under GEMM)
    float xv[2];
    const bool havex = (t + 1 < Sn);
    if (havex) {
#pragma unroll
      for (int j = 0; j < 2; j++)
        if (xr_ok[j]) xv[j] = xr_ptr[j][(t + 1) * In];
    }

    // ---- GEMM: 2 gates x 8 rows over this thread's K half ----
    u64 acc[4][2];
#pragma unroll
    for (int r = 0; r < 4; r++) { acc[r][0] = bias2[0]; acc[r][1] = bias2[1]; }

#pragma unroll
    for (int j = 0; j < KH; j++) {
      const int k = k0 + j;
      const ulonglong2 aa =
          *reinterpret_cast<const ulonglong2*>(&s.act[k][0]);  // rows 0-3
      const ulonglong2 ab =
          *reinterpret_cast<const ulonglong2*>(&s.act[k][4]);  // rows 4-7
      const u64 w0 = pack2(wr0[j], wr0[j]);
      const u64 w1 = pack2(wr1[j], wr1[j]);
      acc[0][0] = fma2(aa.x, w0, acc[0][0]);
      acc[0][1] = fma2(aa.x, w1, acc[0][1]);
      acc[1][0] = fma2(aa.y, w0, acc[1][0]);
      acc[1][1] = fma2(aa.y, w1, acc[1][1]);
      acc[2][0] = fma2(ab.x, w0, acc[2][0]);
      acc[2][1] = fma2(ab.x, w1, acc[2][1]);
      acc[3][0] = fma2(ab.y, w0, acc[3][0]);
      acc[3][1] = fma2(ab.y, w1, acc[3][1]);
    }
#pragma unroll
    for (int r = 0; r < 4; r++) {
      ulonglong2 v;
      v.x = acc[r][0];
      v.y = acc[r][1];
      *reinterpret_cast<ulonglong2*>(&s.part[kh][r][gp][0]) = v;
    }
    __syncthreads();

    // ---- cell update: all 256 threads, 1 packed (unit, rowpair) each ----
    {
      u64 gs[4];  // i/f/g/o gate values, each {row even, row odd}
#pragma unroll
      for (int q = 0; q < 4; q++) {
        const int g   = cu + Hn * q;          // gate index
        const int gpq = g >> 1;
        const int el  = (g & 1) * 2;
        const u64 p0 =
            *reinterpret_cast<const u64*>(&s.part[0][crp][gpq][el]);
        const u64 p1 =
            *reinterpret_cast<const u64*>(&s.part[1][crp][gpq][el]);
        gs[q] = add2(p0, p1);
      }
      float i0, i1, f0, f1, g0, g1, o0, o1, ca, cb;
      unpack2(gs[0], i0, i1);
      unpack2(gs[1], f0, f1);
      unpack2(gs[2], g0, g1);
      unpack2(gs[3], o0, o1);
      unpack2(c2, ca, cb);
      i0 = sigmoid_ap(i0); i1 = sigmoid_ap(i1);
      f0 = sigmoid_ap(f0); f1 = sigmoid_ap(f1);
      g0 = tanh_ap(g0);    g1 = tanh_ap(g1);
      o0 = sigmoid_ap(o0); o1 = sigmoid_ap(o1);
      ca = fmaf(f0, ca, i0 * g0);
      cb = fmaf(f1, cb, i1 * g1);
      c2 = pack2(ca, cb);
      *reinterpret_cast<float2*>(&s.act[cu][2 * crp]) =
          make_float2(o0 * tanh_ap(ca), o1 * tanh_ap(cb));
    }
    if (havex) {
#pragma unroll
      for (int j = 0; j < 2; j++)
        if (xr_ok[j]) s.act[Hn + xr_i2[j]][xr_row2[j]] = xv[j];
    }
    __syncthreads();
  }

  // ---- classifier head: h_last (act[u][row]) -> F1 -> C ----
  {
    const int row = tid >> 5;        // 256 threads = TB*F1 outputs
    const int f   = tid & 31;
    float a1 = b1[f];
#pragma unroll
    for (int u = 0; u < Hn; u++) a1 = fmaf(s.act[u][row], W1[f * Hn + u], a1);
    s.f1[row][f] = fmaxf(a1, 0.0f);
  }
  __syncthreads();
  if (tid < TB * Cn) {
    const int row = tid >> 1;
    const int cl  = tid & 1;
    float o = b2[cl];
#pragma unroll
    for (int f = 0; f < F1n; f++) o = fmaf(s.f1[row][f], W2[cl * F1n + f], o);
    out[(row0 + row) * Cn + cl] = o;
  }
}

}  // namespace

extern "C" void kernel_launch(void* const* d_in, const int* in_sizes, int n_in,
                              void* d_out, int out_size) {
  (void)in_sizes; (void)n_in; (void)out_size;
  const float* x    = (const float*)d_in[0];
  const float* W_ih = (const float*)d_in[1];
  const float* W_hh = (const float*)d_in[2];
  const float* b_ih = (const float*)d_in[3];
  const float* b_hh = (const float*)d_in[4];
  const float* W1   = (const float*)d_in[5];
  const float* b1   = (const float*)d_in[6];
  const float* W2   = (const float*)d_in[7];
  const float* b2   = (const float*)d_in[8];
  float* out = (float*)d_out;

  lstm_fused<<<GRID, NT>>>(x, W_ih, W_hh, b_ih, b_hh, W1, b1, W2, b2, out);
}

// round 6
// speedup vs baseline: 1.3394x; 1.3394x over previous
#include <cuda_runtime.h>

// Fused persistent LSTM + MLP classifier, v4: two-half software pipeline.
// R3/R4/R5 all ~1.07-1.14ms with fma ~= 40% regardless of design: the cell
// update + barriers form a serialized region as long as the GEMM itself.
// v4 splits the block's 8 rows into two independent 4-row halves, staggered:
// phase p = [ GEMM(half g=p&1, step t=p>>1)  ||  cell(half 1-g, step (p-1)>>1) ]
// with ONE barrier per phase. Cell latency hides under the half-GEMM's FFMA2
// stream. Weights stay in registers (114 f/thread, time-invariant).

namespace {

constexpr int Bn   = 1024;
constexpr int Sn   = 512;
constexpr int In   = 50;
constexpr int Hn   = 64;
constexpr int F1n  = 32;
constexpr int Cn   = 2;
constexpr int KTOT = Hn + In;    // 114
constexpr int KH   = 57;         // K half per GEMM thread
constexpr int TB   = 8;          // rows per block (two halves of 4)
constexpr int GRID = Bn / TB;    // 128
constexpr int NT   = 256;

struct Smem {
  float act[2][KTOT][4];        // [half][k][row-in-half]          3648 B
  float part[2][2][2][128][4];  // [half][kh][rp][gp][4]          16384 B
  float f1[TB][F1n];            //                                 1024 B
};

using u64 = unsigned long long;

__device__ __forceinline__ u64 pack2(float lo, float hi) {
  u64 r;
  asm("mov.b64 %0, {%1, %2};" : "=l"(r)
      : "r"(__float_as_uint(lo)), "r"(__float_as_uint(hi)));
  return r;
}
__device__ __forceinline__ void unpack2(u64 v, float& lo, float& hi) {
  unsigned a, b;
  asm("mov.b64 {%0, %1}, %2;" : "=r"(a), "=r"(b) : "l"(v));
  lo = __uint_as_float(a);
  hi = __uint_as_float(b);
}
__device__ __forceinline__ u64 fma2(u64 a, u64 b, u64 c) {
  u64 d;
  asm("fma.rn.f32x2 %0, %1, %2, %3;" : "=l"(d) : "l"(a), "l"(b), "l"(c));
  return d;
}
__device__ __forceinline__ u64 add2(u64 a, u64 b) {
  u64 d;
  asm("add.rn.f32x2 %0, %1, %2;" : "=l"(d) : "l"(a), "l"(b));
  return d;
}
__device__ __forceinline__ float tanh_ap(float x) {
  float y;
  asm("tanh.approx.f32 %0, %1;" : "=f"(y) : "f"(x));
  return y;
}
__device__ __forceinline__ float sigmoid_ap(float x) {
  return fmaf(0.5f, tanh_ap(0.5f * x), 0.5f);
}

__global__ __launch_bounds__(NT, 1) void lstm_fused(
    const float* __restrict__ x,
    const float* __restrict__ W_ih, const float* __restrict__ W_hh,
    const float* __restrict__ b_ih, const float* __restrict__ b_hh,
    const float* __restrict__ W1,   const float* __restrict__ b1,
    const float* __restrict__ W2,   const float* __restrict__ b2,
    float* __restrict__ out) {
  __shared__ Smem s;

  const int tid  = threadIdx.x;
  const int row0 = blockIdx.x * TB;

  // ---- GEMM role: gates 2gp,2gp+1 x K-half kh (applies to whichever half's
  //      phase it is; weights identical across halves) ----
  const int gp = tid & 127;
  const int kh = tid >> 7;
  const int k0 = kh * KH;

  float wr0[KH], wr1[KH];
  {
    const int g0 = 2 * gp, g1 = 2 * gp + 1;
#pragma unroll
    for (int j = 0; j < KH; j++) {
      const int k = k0 + j;
      wr0[j] = (k < Hn) ? W_hh[g0 * Hn + k] : W_ih[g0 * In + (k - Hn)];
      wr1[j] = (k < Hn) ? W_hh[g1 * Hn + k] : W_ih[g1 * In + (k - Hn)];
    }
  }
  u64 bias2[2];
  {
    const float bb0 = (kh == 0) ? b_ih[2 * gp] + b_hh[2 * gp] : 0.0f;
    const float bb1 = (kh == 0) ? b_ih[2 * gp + 1] + b_hh[2 * gp + 1] : 0.0f;
    bias2[0] = pack2(bb0, bb0);
    bias2[1] = pack2(bb1, bb1);
  }

  // ---- cell role: unit cu, rowpair crp, half chf ----
  const int cu  = tid & 63;
  const int crp = (tid >> 6) & 1;
  const int chf = tid >> 7;
  u64 c2 = 0ull;  // cell state {row 2crp, row 2crp+1} of unit cu, half chf

  // ---- x-prefetch role: half xh, 2 slots; 200 slots per half over 128 thr ----
  const int xh = tid >> 7;
  const int si = tid & 127;
  const bool xok = (si < 100);
  int xrl[2], xi[2];
  const float* xptr[2];
#pragma unroll
  for (int j = 0; j < 2; j++) {
    int sl = 2 * si + j;
    int rl = xok ? (sl / In) : 0;
    int i  = xok ? (sl - rl * In) : 0;
    xrl[j] = rl;
    xi[j]  = i;
    xptr[j] = x + (long)(row0 + xh * 4 + rl) * (Sn * In) + i;
  }

  // ---- init: h = 0 for both halves, x_t0 ----
  for (int idx = tid; idx < 2 * Hn * 4; idx += NT) {
    int h = idx / (Hn * 4), r = idx % (Hn * 4);
    s.act[h][r / 4][r & 3] = 0.0f;
  }
  if (xok) {
#pragma unroll
    for (int j = 0; j < 2; j++) s.act[xh][Hn + xi[j]][xrl[j]] = xptr[j][0];
  }
  __syncthreads();

  float xp[2];
  bool  pend = false;

  for (int p = 0; p <= 2 * Sn; p++) {
    const int  g       = p & 1;       // GEMM half this phase
    const int  t       = p >> 1;      // GEMM step
    const bool do_gemm = (p < 2 * Sn);

    // 1) x LDG for half g, step t+1 (own-half threads), latency-first
    if (do_gemm && g == xh && xok && (t + 1 < Sn)) {
#pragma unroll
      for (int j = 0; j < 2; j++) xp[j] = xptr[j][(t + 1) * In];
      pend = true;
    }

    // 2) cell for half c = 1-g (gates produced last phase); threads chf==c
    const int c = 1 - g;
    if (p >= 1 && chf == c) {
      u64 gs[4];
#pragma unroll
      for (int q = 0; q < 4; q++) {
        const int gg  = cu + Hn * q;
        const int gpq = gg >> 1;
        const int el  = (gg & 1) * 2;
        const u64 p0 = *reinterpret_cast<const u64*>(&s.part[c][0][crp][gpq][el]);
        const u64 p1 = *reinterpret_cast<const u64*>(&s.part[c][1][crp][gpq][el]);
        gs[q] = add2(p0, p1);
      }
      float i0, i1, f0, f1, g0, g1, o0, o1, ca, cb;
      unpack2(gs[0], i0, i1);
      unpack2(gs[1], f0, f1);
      unpack2(gs[2], g0, g1);
      unpack2(gs[3], o0, o1);
      unpack2(c2, ca, cb);
      i0 = sigmoid_ap(i0); i1 = sigmoid_ap(i1);
      f0 = sigmoid_ap(f0); f1 = sigmoid_ap(f1);
      g0 = tanh_ap(g0);    g1 = tanh_ap(g1);
      o0 = sigmoid_ap(o0); o1 = sigmoid_ap(o1);
      ca = fmaf(f0, ca, i0 * g0);
      cb = fmaf(f1, cb, i1 * g1);
      c2 = pack2(ca, cb);
      *reinterpret_cast<float2*>(&s.act[c][cu][2 * crp]) =
          make_float2(o0 * tanh_ap(ca), o1 * tanh_ap(cb));
    }

    // 3) GEMM half g, step t: 2 gates x 4 rows over K half (all threads)
    if (do_gemm) {
      u64 acc[2][2];
      acc[0][0] = bias2[0]; acc[0][1] = bias2[1];
      acc[1][0] = bias2[0]; acc[1][1] = bias2[1];
#pragma unroll
      for (int j = 0; j < KH; j++) {
        const int k = k0 + j;
        const ulonglong2 aa =
            *reinterpret_cast<const ulonglong2*>(&s.act[g][k][0]);
        const u64 w0 = pack2(wr0[j], wr0[j]);
        const u64 w1 = pack2(wr1[j], wr1[j]);
        acc[0][0] = fma2(aa.x, w0, acc[0][0]);
        acc[0][1] = fma2(aa.x, w1, acc[0][1]);
        acc[1][0] = fma2(aa.y, w0, acc[1][0]);
        acc[1][1] = fma2(aa.y, w1, acc[1][1]);
      }
#pragma unroll
      for (int r = 0; r < 2; r++) {
        ulonglong2 v;
        v.x = acc[r][0];
        v.y = acc[r][1];
        *reinterpret_cast<ulonglong2*>(&s.part[g][kh][r][gp][0]) = v;
      }
    }

    // 4) commit pending x for half 1-g (loaded previous phase; act[1-g] is
    //    not read by anyone this phase)
    if (xh == 1 - g && pend) {
#pragma unroll
      for (int j = 0; j < 2; j++) s.act[xh][Hn + xi[j]][xrl[j]] = xp[j];
      pend = false;
    }

    __syncthreads();
  }

  // ---- classifier head: h_last in act[row>>2][u][row&3] ----
  {
    const int row = tid >> 5;        // 256 threads = TB*F1 outputs
    const int f   = tid & 31;
    float a1 = b1[f];
#pragma unroll
    for (int u = 0; u < Hn; u++)
      a1 = fmaf(s.act[row >> 2][u][row & 3], W1[f * Hn + u], a1);
    s.f1[row][f] = fmaxf(a1, 0.0f);
  }
  __syncthreads();
  if (tid < TB * Cn) {
    const int row = tid >> 1;
    const int cl  = tid & 1;
    float o = b2[cl];
#pragma unroll
    for (int f = 0; f < F1n; f++) o = fmaf(s.f1[row][f], W2[cl * F1n + f], o);
    out[(row0 + row) * Cn + cl] = o;
  }
}

}  // namespace

extern "C" void kernel_launch(void* const* d_in, const int* in_sizes, int n_in,
                              void* d_out, int out_size) {
  (void)in_sizes; (void)n_in; (void)out_size;
  const float* x    = (const float*)d_in[0];
  const float* W_ih = (const float*)d_in[1];
  const float* W_hh = (const float*)d_in[2];
  const float* b_ih = (const float*)d_in[3];
  const float* b_hh = (const float*)d_in[4];
  const float* W1   = (const float*)d_in[5];
  const float* b1   = (const float*)d_in[6];
  const float* W2   = (const float*)d_in[7];
  const float* b2   = (const float*)d_in[8];
  float* out = (float*)d_out;

  lstm_fused<<<GRID, NT>>>(x, W_ih, W_hh, b_ih, b_hh, W1, b1, W2, b2, out);
}